// round 12
// baseline (speedup 1.0000x reference)
#include <cuda_runtime.h>

#define HH 1024
#define WW 1024
#define NPTS 128
#define BIGD 16384        // sentinel 1D distance; BIGD^2 fits int
#define INFB (1 << 20)    // "side exhausted" bound marker (never squared)

// Process 4 columns [base, base+3] of one row against query col pc.
__device__ __forceinline__ void proc4(float4 v, int base, int pc, int &don, int &doff) {
    int d0 = abs(base     - pc);
    int d1 = abs(base + 1 - pc);
    int d2 = abs(base + 2 - pc);
    int d3 = abs(base + 3 - pc);
    if (v.x != 0.0f) don = min(don, d0); else doff = min(doff, d0);
    if (v.y != 0.0f) don = min(don, d1); else doff = min(doff, d1);
    if (v.z != 0.0f) don = min(don, d2); else doff = min(doff, d2);
    if (v.w != 0.0f) don = min(don, d3); else doff = min(doff, d3);
}

// Lazy column extension beyond the preloaded [c0, c0+15] window.
// Invariants: L == 3 (mod 4), R == 0 (mod 4) -> aligned, in-bounds accesses.
__device__ __forceinline__ void extend_cols(const float* __restrict__ rowf,
                                            int pc, int c0, int &don, int &doff) {
    int L = c0 - 1;
    int R = c0 + 16;
    #pragma unroll 1
    while (true) {
        int bl = (L >= 0) ? (pc - L) : 0x3FFFFFFF;
        int br = (R < WW) ? (R - pc) : 0x3FFFFFFF;
        int bound = min(bl, br);
        if (don <= bound && doff <= bound) break;   // certain once both sides exhausted
        if (bl <= br) {
            float4 v = *reinterpret_cast<const float4*>(rowf + (L - 3));
            proc4(v, L - 3, pc, don, doff);
            L -= 4;
        } else {
            float4 v = *reinterpret_cast<const float4*>(rowf + R);
            proc4(v, R, pc, don, doff);
            R += 4;
        }
    }
}

// Full single-row scan (used only in the rare fallback rounds).
__device__ __forceinline__ void scan_row_full(const float* __restrict__ hd,
                                              int r, int pc, int c0,
                                              int &don, int &doff) {
    const float* rowf = hd + r * WW;
    const float4* p = reinterpret_cast<const float4*>(rowf + c0);
    float4 v0 = p[0], v1 = p[1], v2 = p[2], v3 = p[3];
    don = BIGD; doff = BIGD;
    proc4(v0, c0,      pc, don, doff);
    proc4(v1, c0 + 4,  pc, don, doff);
    proc4(v2, c0 + 8,  pc, don, doff);
    proc4(v3, c0 + 12, pc, don, doff);
    extend_cols(rowf, pc, c0, don, doff);
}

// One launch, one block, 1024 threads = 128 points x 8 slots, 2 rows/slot.
// Round 0 covers rows pr-8..pr+7 with ALL loads issued before processing
// (single memory hop). Exact certificates guarantee equality with the full
// 2D min; fallback ring rounds handle the ~0.2%-per-point residual.
__global__ void __launch_bounds__(1024, 1)
roadloss_kernel(const float* __restrict__ hd,
                const int*   __restrict__ pred,
                float*       __restrict__ out) {
    int tid = threadIdx.x;
    int n   = tid >> 3;           // point 0..127
    int rl  = tid & 7;            // slot 0..7

    int pr = pred[2 * n];         // component 0: vs rows in d2
    int pc = pred[2 * n + 1];     // component 1: vs cols in d2

    // Loss-neighbor prefetch (tid<128, one point each), overlaps everything.
    // Reference indexes hd_map[py-1..py, px-1..px] with px=pred[:,0],
    // py=pred[:,1] (swapped roles), JAX-clamped.
    float nv0 = 0.f, nv1 = 0.f, nv2 = 0.f, nv3 = 0.f;
    if (tid < NPTS) {
        int px = pred[2 * tid];
        int py = pred[2 * tid + 1];
        int r0 = min(max(py - 1, 0), HH - 1);
        int r1 = min(max(py,     0), HH - 1);
        int cc0 = min(max(px - 1, 0), WW - 1);
        int cc1 = min(max(px,     0), WW - 1);
        nv0 = hd[r0 * WW + cc0];
        nv1 = hd[r0 * WW + cc1];
        nv2 = hd[r1 * WW + cc0];
        nv3 = hd[r1 * WW + cc1];
    }

    unsigned int gmask = 0xFFu << ((tid & 31) & ~7);   // 8-lane group mask

    // 16-col aligned window around pc.
    int c0 = (pc - 8) & ~3;
    if (c0 < 0) c0 = 0;
    if (c0 > WW - 16) c0 = WW - 16;

    // Round 0: two rows per thread, offsets covering [-8, 7].
    int offA = rl - 4;                               // [-4..3]
    int offB = (rl < 4) ? (rl - 8) : rl;             // [-8..-5] u [4..7]
    int rA = pr + offA;
    int rB = pr + offB;
    bool vA = (rA >= 0) && (rA < HH);
    bool vB = (rB >= 0) && (rB < HH);
    int rAc = min(max(rA, 0), HH - 1);
    int rBc = min(max(rB, 0), HH - 1);
    const float* rowfA = hd + rAc * WW;
    const float* rowfB = hd + rBc * WW;
    const float4* pA = reinterpret_cast<const float4*>(rowfA + c0);
    const float4* pB = reinterpret_cast<const float4*>(rowfB + c0);

    // Issue all 8 loads before touching any of them.
    float4 a0 = pA[0], a1 = pA[1], a2 = pA[2], a3 = pA[3];
    float4 b0 = pB[0], b1 = pB[1], b2 = pB[2], b3 = pB[3];

    int donA = BIGD, doffA = BIGD, donB = BIGD, doffB = BIGD;
    proc4(a0, c0,      pc, donA, doffA);
    proc4(a1, c0 + 4,  pc, donA, doffA);
    proc4(a2, c0 + 8,  pc, donA, doffA);
    proc4(a3, c0 + 12, pc, donA, doffA);
    proc4(b0, c0,      pc, donB, doffB);
    proc4(b1, c0 + 4,  pc, donB, doffB);
    proc4(b2, c0 + 8,  pc, donB, doffB);
    proc4(b3, c0 + 12, pc, donB, doffB);
    if (vA) extend_cols(rowfA, pc, c0, donA, doffA);   // rare (~0.3%/row)
    if (vB) extend_cols(rowfB, pc, c0, donB, doffB);

    int vonA  = vA ? (offA * offA + donA * donA)   : 0x3FFFFFFF;
    int voffA = vA ? (offA * offA + doffA * doffA) : 0x3FFFFFFF;
    int vonB  = vB ? (offB * offB + donB * donB)   : 0x3FFFFFFF;
    int voffB = vB ? (offB * offB + doffB * doffB) : 0x3FFFFFFF;
    int von  = min(vonA, vonB);
    int voff = min(voffA, voffB);

    #pragma unroll
    for (int o = 4; o > 0; o >>= 1) {
        von  = min(von,  __shfl_xor_sync(gmask, von,  o));
        voff = min(voff, __shfl_xor_sync(gmask, voff, o));
    }
    int best_on  = von;
    int best_off = voff;

    // Fallback ring rounds (rare): extend row coverage 8 up + 8 down per round.
    int up_hi   = 7;     // highest covered offset
    int down_lo = -8;    // lowest covered offset
    #pragma unroll 1
    for (int round = 0; round < 130; round++) {
        int bu = (pr + up_hi + 1 <= HH - 1) ? (up_hi + 1)  : INFB;
        int bd = (pr + down_lo - 1 >= 0)    ? (1 - down_lo) : INFB;
        int bound = min(bu, bd);
        if (bound >= INFB) break;                        // map exhausted
        if (best_on <= bound * bound && best_off <= bound * bound) break;

        int oa = up_hi + 1 + rl;        // up rows
        int ob = down_lo - 1 - rl;      // down rows
        int ra = pr + oa, rb = pr + ob;
        bool va = (ra >= 0) && (ra < HH);
        bool vb = (rb >= 0) && (rb < HH);
        int na = 0x3FFFFFFF, fa = 0x3FFFFFFF, nb2 = 0x3FFFFFFF, fb = 0x3FFFFFFF;
        if (va) {
            int d1, d2; scan_row_full(hd, ra, pc, c0, d1, d2);
            na = oa * oa + d1 * d1; fa = oa * oa + d2 * d2;
        }
        if (vb) {
            int d1, d2; scan_row_full(hd, rb, pc, c0, d1, d2);
            nb2 = ob * ob + d1 * d1; fb = ob * ob + d2 * d2;
        }
        int rn = min(na, nb2), rf = min(fa, fb);
        #pragma unroll
        for (int o = 4; o > 0; o >>= 1) {
            rn = min(rn, __shfl_xor_sync(gmask, rn, o));
            rf = min(rf, __shfl_xor_sync(gmask, rf, o));
        }
        best_on  = min(best_on,  rn);
        best_off = min(best_off, rf);
        up_hi   += 8;
        down_lo -= 8;
    }

    __shared__ int s_on[NPTS];
    __shared__ int s_off[NPTS];
    if (rl == 0) { s_on[n] = best_on; s_off[n] = best_off; }
    __syncthreads();

    // ---- Loss + mean (threads 0..127; neighbor values already in regs) ----
    __shared__ float s_sum[NPTS];
    if (tid < NPTS) {
        int px = pred[2 * tid];
        int py = pred[2 * tid + 1];
        bool outside_frame = (px < 0) || (px > HH) || (py < 0) || (py > WW);
        float loss = 0.0f;
        if (!outside_frame) {
            bool road = (nv0 == 1.0f) || (nv1 == 1.0f) ||
                        (nv2 == 1.0f) || (nv3 == 1.0f);
            const float K1 = 21.7f;
            const float LN2_OVER_K2 = 0.69314718055994531f / 40.0f;
            loss = road ? expf(sqrtf((float)s_off[tid]) * LN2_OVER_K2)
                        : expf(-(float)s_on[tid] / K1);
        }
        s_sum[tid] = loss;
    }
    __syncthreads();
    if (tid < 64) s_sum[tid] += s_sum[tid + 64];
    __syncthreads();
    if (tid < 32) {
        float v = s_sum[tid] + s_sum[tid + 32];
        #pragma unroll
        for (int o = 16; o > 0; o >>= 1)
            v += __shfl_xor_sync(0xFFFFFFFFu, v, o);
        if (tid == 0) out[0] = v * (1.0f / (float)NPTS);
    }
}

extern "C" void kernel_launch(void* const* d_in, const int* in_sizes, int n_in,
                              void* d_out, int out_size) {
    const float* hd  = (const float*)d_in[0];
    const int* pred  = (const int*)d_in[1];
    float* out       = (float*)d_out;
    roadloss_kernel<<<1, 1024>>>(hd, pred, out);
}

// round 13
// speedup vs baseline: 2.0223x; 2.0223x over previous
#include <cuda_runtime.h>

#define HH 1024
#define WW 1024
#define NPTS 128
#define BIGD 16384        // sentinel 1D distance; BIGD^2 fits int

// One launch, one block, 1024 threads = 128 points x 8 row-slots.
// All work serializes on one SM, so the design minimizes ISSUED INSTRUCTIONS:
// thread-local ring certificates (no intra-loop reductions), one final masked
// REDUX per point, lean 8-col window scan with rare lazy extension.
__global__ void __launch_bounds__(1024, 1)
roadloss_kernel(const float* __restrict__ hd,
                const int*   __restrict__ pred,
                float*       __restrict__ out) {
    int tid = threadIdx.x;
    int n   = tid >> 3;           // point 0..127
    int rl  = tid & 7;            // row-slot 0..7
    bool up = (rl < 4);

    int2 p = reinterpret_cast<const int2*>(pred)[n];
    int pr = p.x;                 // vs rows in d2
    int pc = p.y;                 // vs cols in d2

    // Loss-neighbor prefetch (tid<128, one point each) — overlaps the search.
    // Reference indexes hd_map[py-1..py, px-1..px] with px=pred[:,0],
    // py=pred[:,1] (roles swapped vs distance), JAX-clamped.
    float nv0 = 0.f, nv1 = 0.f, nv2 = 0.f, nv3 = 0.f;
    int2 pl = make_int2(0, 0);
    if (tid < NPTS) {
        pl = reinterpret_cast<const int2*>(pred)[tid];
        int px = pl.x, py = pl.y;
        int r0 = min(max(py - 1, 0), HH - 1);
        int r1 = min(max(py,     0), HH - 1);
        int cc0 = min(max(px - 1, 0), WW - 1);
        int cc1 = min(max(px,     0), WW - 1);
        nv0 = hd[r0 * WW + cc0];
        nv1 = hd[r0 * WW + cc1];
        nv2 = hd[r1 * WW + cc0];
        nv3 = hd[r1 * WW + cc1];
    }

    unsigned int gmask = 0xFFu << ((tid & 31) & ~7);   // aligned 8-lane group

    // Aligned 8-col window containing pc.
    int c0 = (pc - 4) & ~3;
    if (c0 < 0) c0 = 0;
    if (c0 > WW - 8) c0 = WW - 8;

    int priv_on  = 0x3FFFFFFF;
    int priv_off = 0x3FFFFFFF;

    // Thread-local ring: this thread covers offsets {4j+rl} (up) or
    // {-(4j+rl-3)} (down). Unscanned-by-this-thread rows have |dr| >= 4(j+1),
    // so stopping at priv <= (4(j+1))^2 is individually sound, and the group
    // min of sound private answers equals the exact global min.
    #pragma unroll 1
    for (int j = 0; j < 256; j++) {
        int off = up ? (4 * j + rl) : -(4 * j + (rl - 3));
        int r   = pr + off;

        if (r >= 0 && r < HH) {
            const float* rowf = hd + r * WW;
            float4 a = *reinterpret_cast<const float4*>(rowf + c0);
            float4 b = *reinterpret_cast<const float4*>(rowf + c0 + 4);

            int don = BIGD, doff = BIGD;
            {
                float w[8] = {a.x, a.y, a.z, a.w, b.x, b.y, b.z, b.w};
                #pragma unroll
                for (int t = 0; t < 8; t++) {
                    int d = abs(c0 + t - pc);
                    if (w[t] != 0.0f) don = min(don, d); else doff = min(doff, d);
                }
            }
            // Lazy column extension (rare: ~5.7% on-side, ~0 off-side).
            // Invariants: L == 3 (mod 4), R == 0 (mod 4).
            int L = c0 - 1;
            int R = c0 + 8;
            #pragma unroll 1
            while (true) {
                int bl = (L >= 0) ? (pc - L) : 0x3FFFFFFF;
                int br = (R < WW) ? (R - pc) : 0x3FFFFFFF;
                int bound = min(bl, br);
                if (don <= bound && doff <= bound) break;
                if (bl <= br) {
                    float4 v = *reinterpret_cast<const float4*>(rowf + (L - 3));
                    int base = L - 3;
                    float w[4] = {v.x, v.y, v.z, v.w};
                    #pragma unroll
                    for (int t = 0; t < 4; t++) {
                        int d = pc - (base + t);
                        if (w[t] != 0.0f) don = min(don, d); else doff = min(doff, d);
                    }
                    L -= 4;
                } else {
                    float4 v = *reinterpret_cast<const float4*>(rowf + R);
                    float w[4] = {v.x, v.y, v.z, v.w};
                    #pragma unroll
                    for (int t = 0; t < 4; t++) {
                        int d = (R + t) - pc;
                        if (w[t] != 0.0f) don = min(don, d); else doff = min(doff, d);
                    }
                    R += 4;
                }
            }
            int dr2 = off * off;
            priv_on  = min(priv_on,  dr2 + don * don);    // exact in int
            priv_off = min(priv_off, dr2 + doff * doff);
        }

        // Thread-local certificate.
        int nb  = 4 * (j + 1);
        int nb2 = nb * nb;
        if (priv_on <= nb2 && priv_off <= nb2) break;
        // This thread's remaining rows all out of range?
        int next = up ? (pr + 4 * (j + 1) + rl) : (pr - (4 * (j + 1) + (rl - 3)));
        if (next < 0 || next >= HH) break;
    }

    // One masked REDUX pair per point (lanes reconverge here).
    int best_on  = __reduce_min_sync(gmask, priv_on);
    int best_off = __reduce_min_sync(gmask, priv_off);

    __shared__ int s_on[NPTS];
    __shared__ int s_off[NPTS];
    if (rl == 0) { s_on[n] = best_on; s_off[n] = best_off; }
    __syncthreads();

    // ---- Loss + mean (threads 0..127; neighbor values already in regs) ----
    __shared__ float s_sum[NPTS];
    if (tid < NPTS) {
        int px = pl.x, py = pl.y;
        bool outside_frame = (px < 0) || (px > HH) || (py < 0) || (py > WW);
        float loss = 0.0f;
        if (!outside_frame) {
            bool road = (nv0 == 1.0f) || (nv1 == 1.0f) ||
                        (nv2 == 1.0f) || (nv3 == 1.0f);
            const float K1 = 21.7f;
            const float LN2_OVER_K2 = 0.69314718055994531f / 40.0f;
            loss = road ? expf(sqrtf((float)s_off[tid]) * LN2_OVER_K2)
                        : expf(-(float)s_on[tid] / K1);
        }
        s_sum[tid] = loss;
    }
    __syncthreads();
    if (tid < 64) s_sum[tid] += s_sum[tid + 64];
    __syncthreads();
    if (tid < 32) {
        float v = s_sum[tid] + s_sum[tid + 32];
        #pragma unroll
        for (int o = 16; o > 0; o >>= 1)
            v += __shfl_xor_sync(0xFFFFFFFFu, v, o);
        if (tid == 0) out[0] = v * (1.0f / (float)NPTS);
    }
}

extern "C" void kernel_launch(void* const* d_in, const int* in_sizes, int n_in,
                              void* d_out, int out_size) {
    const float* hd  = (const float*)d_in[0];
    const int* pred  = (const int*)d_in[1];
    float* out       = (float*)d_out;
    roadloss_kernel<<<1, 1024>>>(hd, pred, out);
}

// round 14
// speedup vs baseline: 2.3175x; 1.1460x over previous
#include <cuda_runtime.h>

#define HH 1024
#define WW 1024
#define NPTS 128
#define NBLK 32
#define PPB 4             // points per block
#define TPB 512           // 4 points x 128 row-slots
#define BIGD 16384        // sentinel 1D distance
#define INF_I 0x3FFFFFFF
#define INF_B (1 << 20)

// Cross-block handoff: one float + one flag per block, each on its own 128B line.
__device__ volatile float g_part[NBLK * 32];
__device__ volatile int   g_flag[NBLK * 32];   // zero-init; block 0 resets each run

// Exact nearest on/off column distance in row `rowf` from query col pc.
// 8-col preloaded window + lazy aligned extension (L == 3 mod 4, R == 0 mod 4).
__device__ __forceinline__ void scan_cols(const float* __restrict__ rowf,
                                          int pc, int c0, int &don, int &doff) {
    float4 a = *reinterpret_cast<const float4*>(rowf + c0);
    float4 b = *reinterpret_cast<const float4*>(rowf + c0 + 4);
    don = BIGD; doff = BIGD;
    {
        float w[8] = {a.x, a.y, a.z, a.w, b.x, b.y, b.z, b.w};
        #pragma unroll
        for (int t = 0; t < 8; t++) {
            int d = abs(c0 + t - pc);
            if (w[t] != 0.0f) don = min(don, d); else doff = min(doff, d);
        }
    }
    int L = c0 - 1;
    int R = c0 + 8;
    #pragma unroll 1
    while (true) {
        int bl = (L >= 0) ? (pc - L) : INF_I;
        int br = (R < WW) ? (R - pc) : INF_I;
        int bound = min(bl, br);
        if (don <= bound && doff <= bound) break;    // certain once both exhausted
        if (bl <= br) {
            float4 v = *reinterpret_cast<const float4*>(rowf + (L - 3));
            float u[4] = {v.x, v.y, v.z, v.w};
            #pragma unroll
            for (int t = 0; t < 4; t++) {
                int d = pc - (L - 3 + t);
                if (u[t] != 0.0f) don = min(don, d); else doff = min(doff, d);
            }
            L -= 4;
        } else {
            float4 v = *reinterpret_cast<const float4*>(rowf + R);
            float u[4] = {v.x, v.y, v.z, v.w};
            #pragma unroll
            for (int t = 0; t < 4; t++) {
                int d = (R + t) - pc;
                if (u[t] != 0.0f) don = min(don, d); else doff = min(doff, d);
            }
            R += 4;
        }
    }
}

__global__ void __launch_bounds__(TPB, 1)
roadloss_kernel(const float* __restrict__ hd,
                const int*   __restrict__ pred,
                float*       __restrict__ out) {
    int tid  = threadIdx.x;
    int b    = blockIdx.x;
    int pn   = tid >> 7;          // local point 0..3
    int slot = tid & 127;         // row slot 0..127 -> offset slot-64
    int gpt  = b * PPB + pn;      // global point

    int2 p = reinterpret_cast<const int2*>(pred)[gpt];
    int pr = p.x;                 // vs rows in d2
    int pc = p.y;                 // vs cols in d2

    // Loss-neighbor prefetch for this block's 4 points (tid<4, one each).
    // Reference indexes hd_map[py-1..py, px-1..px] with px=pred[:,0],
    // py=pred[:,1] (roles swapped vs distance), JAX-clamped.
    float nv0 = 0.f, nv1 = 0.f, nv2 = 0.f, nv3 = 0.f;
    int2 pl = make_int2(0, 0);
    if (tid < PPB) {
        pl = reinterpret_cast<const int2*>(pred)[b * PPB + tid];
        int px = pl.x, py = pl.y;
        int r0 = min(max(py - 1, 0), HH - 1);
        int r1 = min(max(py,     0), HH - 1);
        int cA = min(max(px - 1, 0), WW - 1);
        int cB = min(max(px,     0), WW - 1);
        nv0 = hd[r0 * WW + cA];
        nv1 = hd[r0 * WW + cB];
        nv2 = hd[r1 * WW + cA];
        nv3 = hd[r1 * WW + cB];
    }

    int c0 = (pc - 4) & ~3;
    if (c0 < 0) c0 = 0;
    if (c0 > WW - 8) c0 = WW - 8;

    // ---- Single round: offsets -64..63, one row per thread ----
    int off = slot - 64;
    int r   = pr + off;
    int von = INF_I, voff = INF_I;
    if (r >= 0 && r < HH) {
        int dn, df;
        scan_cols(hd + r * WW, pc, c0, dn, df);
        von  = off * off + dn * dn;      // exact in int
        voff = off * off + df * df;
    }
    von  = __reduce_min_sync(0xFFFFFFFFu, von);   // warp lies within one point
    voff = __reduce_min_sync(0xFFFFFFFFu, voff);

    __shared__ int s_won[16], s_woff[16];
    __shared__ int s_bon[PPB], s_boff[PPB];
    int wid = tid >> 5, lane = tid & 31;
    if (lane == 0) { s_won[wid] = von; s_woff[wid] = voff; }
    __syncthreads();
    if (tid < PPB) {
        int w0 = 4 * tid;
        s_bon[tid]  = min(min(s_won[w0],  s_won[w0 + 1]),  min(s_won[w0 + 2],  s_won[w0 + 3]));
        s_boff[tid] = min(min(s_woff[w0], s_woff[w0 + 1]), min(s_woff[w0 + 2], s_woff[w0 + 3]));
    }

    // ---- Block-uniform fallback ring (P ~ 0; kept for exactness) ----
    int low = -64, high = 63;
    #pragma unroll 1
    while (true) {
        int need = 0;
        if (tid < PPB) {
            int prt = pl.x;
            int bu = (prt + high + 1 <= HH - 1) ? (high + 1) : INF_B;
            int bd = (prt + low  - 1 >= 0)      ? (1 - low)  : INF_B;
            int bound = min(bu, bd);
            if (bound < INF_B)
                need = (s_bon[tid] > bound * bound) || (s_boff[tid] > bound * bound);
        }
        if (!__syncthreads_or(need)) break;    // also syncs s_bon/s_boff
        int off2 = (slot < 64) ? (high + 1 + slot) : (low - 1 - (slot - 64));
        int r2 = pr + off2;
        int v1 = INF_I, v2 = INF_I;
        if (r2 >= 0 && r2 < HH) {
            int dn, df;
            scan_cols(hd + r2 * WW, pc, c0, dn, df);
            v1 = off2 * off2 + dn * dn;
            v2 = off2 * off2 + df * df;
        }
        v1 = __reduce_min_sync(0xFFFFFFFFu, v1);
        v2 = __reduce_min_sync(0xFFFFFFFFu, v2);
        if (lane == 0) { s_won[wid] = v1; s_woff[wid] = v2; }
        __syncthreads();
        if (tid < PPB) {
            int w0 = 4 * tid;
            s_bon[tid]  = min(s_bon[tid],
                min(min(s_won[w0],  s_won[w0 + 1]),  min(s_won[w0 + 2],  s_won[w0 + 3])));
            s_boff[tid] = min(s_boff[tid],
                min(min(s_woff[w0], s_woff[w0 + 1]), min(s_woff[w0 + 2], s_woff[w0 + 3])));
        }
        high += 64; low -= 64;
    }

    // ---- Per-point loss + block partial (warp 0 only) ----
    float partial = 0.0f;
    if (wid == 0) {
        if (tid < PPB) {
            int px = pl.x, py = pl.y;
            bool oframe = (px < 0) || (px > HH) || (py < 0) || (py > WW);
            if (!oframe) {
                bool road = (nv0 == 1.0f) || (nv1 == 1.0f) ||
                            (nv2 == 1.0f) || (nv3 == 1.0f);
                const float K1 = 21.7f;
                const float LN2_OVER_K2 = 0.69314718055994531f / 40.0f;
                partial = road ? expf(sqrtf((float)s_boff[tid]) * LN2_OVER_K2)
                               : expf(-(float)s_bon[tid] / K1);
            }
        }
        // sum lanes 0..3 into lane 0 (others contribute 0)
        partial += __shfl_xor_sync(0xFFFFFFFFu, partial, 1);
        partial += __shfl_xor_sync(0xFFFFFFFFu, partial, 2);

        if (b != 0) {
            if (lane == 0) {
                g_part[b * 32] = partial;
                __threadfence();              // partial visible before flag
                g_flag[b * 32] = 1;           // distinct 128B line per block
            }
        } else {
            // Block 0: parallel per-lane polling of distinct lines, no atomics.
            if (lane >= 1) {
                while (g_flag[lane * 32] == 0) { }
            }
            __syncwarp();
            __threadfence();                  // acquire before reading partials
            float v = (lane == 0) ? partial : g_part[lane * 32];
            #pragma unroll
            for (int o = 16; o > 0; o >>= 1)
                v += __shfl_xor_sync(0xFFFFFFFFu, v, o);
            if (lane == 0) out[0] = v * (1.0f / (float)NPTS);
            // reset flags for next graph replay (all writers observed done)
            if (lane >= 1) g_flag[lane * 32] = 0;
        }
    }
}

extern "C" void kernel_launch(void* const* d_in, const int* in_sizes, int n_in,
                              void* d_out, int out_size) {
    const float* hd  = (const float*)d_in[0];
    const int* pred  = (const int*)d_in[1];
    float* out       = (float*)d_out;
    roadloss_kernel<<<NBLK, TPB>>>(hd, pred, out);
}